// round 5
// baseline (speedup 1.0000x reference)
#include <cuda_runtime.h>
#include <math.h>

#define NN      100000
#define EE      1600000
#define DIN_    128
#define HID_    64
#define DOUT_   40
#define NLAYERS 8
#define NB1     ((NN + 511) / 512)   // 196 scan blocks

// ---------------- scratch (device globals; no allocation allowed) ----------
__device__ int    g_degi[NN];
__device__ float  g_dinv[NN];
__device__ int    g_off[NN];
__device__ int    g_cur[NN];
__device__ int    g_bsum[256];
__device__ int    g_boff[256];
__device__ int    g_csrs[EE];
__device__ float  g_csrw[EE];
__device__ float4 g_h0[NN * 16];
__device__ float4 g_h[NN * 16];
__device__ float4 g_agg[NN * 16];
__device__ float  g_M[NLAYERS * HID_ * HID_];

// ---------------- graph prep (edge_index is INT32: jax default, no x64) ----
__global__ void deg_zero_k() {
    int i = blockIdx.x * blockDim.x + threadIdx.x;
    if (i < NN) g_degi[i] = 0;
}

__global__ void deg_count_k(const int* __restrict__ ei) {
    int e = blockIdx.x * blockDim.x + threadIdx.x;
    if (e < EE) {
        int d = ei[EE + e];
        if (d >= 0 && d < NN) atomicAdd(&g_degi[d], 1);
    }
}

__global__ void dinv_k() {
    int i = blockIdx.x * blockDim.x + threadIdx.x;
    if (i < NN) g_dinv[i] = rsqrtf((float)g_degi[i] + 1.0f);  // +1 self-loop
}

// --- exclusive scan over g_degi -> g_off: padded Hillis-Steele (no neg idx) -
__global__ void scan1_k() {
    __shared__ int s[1024];
    int t = threadIdx.x;
    int i = blockIdx.x * 512 + t;
    int v = (i < NN) ? g_degi[i] : 0;
    s[t] = 0;            // lower pad
    s[512 + t] = v;
    __syncthreads();
#pragma unroll
    for (int d = 1; d < 512; d <<= 1) {
        int u = s[512 + t - d];
        __syncthreads();
        s[512 + t] += u;
        __syncthreads();
    }
    if (i < NN) g_off[i] = s[512 + t] - v;           // local exclusive
    if (t == 511) g_bsum[blockIdx.x] = s[512 + 511]; // block total
}

__global__ void scan2_k() {
    __shared__ int s[512];
    int t = threadIdx.x;
    int v = (t < NB1) ? g_bsum[t] : 0;
    s[t] = 0;
    s[256 + t] = v;
    __syncthreads();
#pragma unroll
    for (int d = 1; d < 256; d <<= 1) {
        int u = s[256 + t - d];
        __syncthreads();
        s[256 + t] += u;
        __syncthreads();
    }
    g_boff[t] = s[256 + t] - v;                       // exclusive
}

__global__ void scan3_k() {
    int i = blockIdx.x * 512 + threadIdx.x;
    if (i < NN) {
        int o = g_off[i] + g_boff[blockIdx.x];
        g_off[i] = o;
        g_cur[i] = o;
    }
}

__global__ void fill_k(const int* __restrict__ ei) {
    int e = blockIdx.x * blockDim.x + threadIdx.x;
    if (e < EE) {
        int s = ei[e];
        int d = ei[EE + e];
        if (s >= 0 && s < NN && d >= 0 && d < NN) {
            int pos = atomicAdd(&g_cur[d], 1);
            g_csrs[pos] = s;
            g_csrw[pos] = g_dinv[s] * g_dinv[d];
        }
    }
}

// M_l = (1-beta)*I + beta*W_l
__global__ void mfuse_k(const float* __restrict__ cw) {
    int idx = blockIdx.x * blockDim.x + threadIdx.x;
    if (idx < NLAYERS * HID_ * HID_) {
        int l = idx >> 12;
        int rc = idx & 4095;
        int r = rc >> 6, c = rc & 63;
        float beta = logf(0.5f / (float)(l + 1) + 1.0f);
        float v = beta * cw[idx];
        if (r == c) v += 1.0f - beta;
        g_M[idx] = v;
    }
}

// ---------------- aggregation: CSR gather, fused with residual -------------
// g_agg[row] = 0.9*( dinv[row]^2 * h[row] + sum_e w_e * h[src_e] ) + 0.1*h0[row]
__global__ void __launch_bounds__(256) gather_k(int use_h0) {
    int gid = blockIdx.x * 256 + threadIdx.x;
    int row = gid >> 4;
    int j = gid & 15;
    if (row >= NN) return;

    const float4* __restrict__ h4 = use_h0 ? g_h0 : g_h;

    float di = g_dinv[row];
    float ws = di * di;
    float4 hv = h4[row * 16 + j];
    float4 acc = make_float4(ws * hv.x, ws * hv.y, ws * hv.z, ws * hv.w);

    int beg = g_off[row];
    int end = beg + g_degi[row];
    int e = beg;
    for (; e + 1 < end; e += 2) {
        int s0 = g_csrs[e];
        int s1 = g_csrs[e + 1];
        float w0 = g_csrw[e];
        float w1 = g_csrw[e + 1];
        float4 v0 = h4[s0 * 16 + j];
        float4 v1 = h4[s1 * 16 + j];
        acc.x += w0 * v0.x + w1 * v1.x;
        acc.y += w0 * v0.y + w1 * v1.y;
        acc.z += w0 * v0.z + w1 * v1.z;
        acc.w += w0 * v0.w + w1 * v1.w;
    }
    if (e < end) {
        int s0 = g_csrs[e];
        float w0 = g_csrw[e];
        float4 v0 = h4[s0 * 16 + j];
        acc.x += w0 * v0.x;
        acc.y += w0 * v0.y;
        acc.z += w0 * v0.z;
        acc.w += w0 * v0.w;
    }

    float4 h0v = g_h0[row * 16 + j];
    g_agg[row * 16 + j] = make_float4(0.9f * acc.x + 0.1f * h0v.x,
                                      0.9f * acc.y + 0.1f * h0v.y,
                                      0.9f * acc.z + 0.1f * h0v.z,
                                      0.9f * acc.w + 0.1f * h0v.w);
}

// ---------------- fused tiled GEMM (C = 64 cols) ---------------------------
// AMODE 0: A = Aext (x, K=KT).  AMODE 1: A = g_agg (K=64), B = M[layer].
template <int KT, int AMODE, bool OUT0, bool BIAS>
__global__ void __launch_bounds__(256) gemm_k(
    const float* __restrict__ Aext,
    const float* __restrict__ Bext,
    const float* __restrict__ bias,
    int layer)
{
    __shared__ float As[64 * 68];   // transposed: As[k][r], pad 68
    __shared__ float Bs[64 * 64];
    __shared__ float bsh[64];

    const float* B = (AMODE == 1) ? (g_M + layer * (HID_ * HID_)) : Bext;

    int tid = threadIdx.x;
    int tx = tid & 15;
    int ty = tid >> 4;
    int row0 = blockIdx.x << 6;

    if (BIAS && tid < 64) bsh[tid] = bias[tid];

    float acc[4][4] = {};

#pragma unroll
    for (int kc = 0; kc < KT; kc += 64) {
        for (int i = tid; i < 64 * 64; i += 256)
            Bs[i] = B[kc * 64 + i];

        {
            int r = tid >> 2;
            int fq = tid & 3;
            int grow = row0 + r;
            bool ok = grow < NN;
#pragma unroll
            for (int q = 0; q < 4; q++) {
                int f4 = fq * 4 + q;
                float4 v = make_float4(0.f, 0.f, 0.f, 0.f);
                if (ok) {
                    if (AMODE == 1) {
                        v = g_agg[grow * 16 + f4];
                    } else {
                        v = ((const float4*)Aext)[grow * (KT / 4) + (kc >> 2) + f4];
                    }
                }
                int kk = f4 << 2;
                As[(kk + 0) * 68 + r] = v.x;
                As[(kk + 1) * 68 + r] = v.y;
                As[(kk + 2) * 68 + r] = v.z;
                As[(kk + 3) * 68 + r] = v.w;
            }
        }
        __syncthreads();

#pragma unroll 16
        for (int k = 0; k < 64; k++) {
            float4 a4 = *(const float4*)&As[k * 68 + (ty << 2)];
            float4 b4 = *(const float4*)&Bs[(k << 6) + (tx << 2)];
            acc[0][0] += a4.x * b4.x; acc[0][1] += a4.x * b4.y;
            acc[0][2] += a4.x * b4.z; acc[0][3] += a4.x * b4.w;
            acc[1][0] += a4.y * b4.x; acc[1][1] += a4.y * b4.y;
            acc[1][2] += a4.y * b4.z; acc[1][3] += a4.y * b4.w;
            acc[2][0] += a4.z * b4.x; acc[2][1] += a4.z * b4.y;
            acc[2][2] += a4.z * b4.z; acc[2][3] += a4.z * b4.w;
            acc[3][0] += a4.w * b4.x; acc[3][1] += a4.w * b4.y;
            acc[3][2] += a4.w * b4.z; acc[3][3] += a4.w * b4.w;
        }
        __syncthreads();
    }

    float4* C = OUT0 ? g_h0 : g_h;
#pragma unroll
    for (int i = 0; i < 4; i++) {
        int r = row0 + (ty << 2) + i;
        if (r < NN) {
            float4 o = make_float4(acc[i][0], acc[i][1], acc[i][2], acc[i][3]);
            if (BIAS) {
                o.x += bsh[tx * 4 + 0];
                o.y += bsh[tx * 4 + 1];
                o.z += bsh[tx * 4 + 2];
                o.w += bsh[tx * 4 + 3];
            }
            o.x = fmaxf(o.x, 0.f);
            o.y = fmaxf(o.y, 0.f);
            o.z = fmaxf(o.z, 0.f);
            o.w = fmaxf(o.w, 0.f);
            C[r * 16 + tx] = o;
        }
    }
}

// ---------------- final GEMM: out = h @ W2 + b2  ([N,64]@[64,40]) ----------
__global__ void __launch_bounds__(256) final_k(
    const float* __restrict__ W2, const float* __restrict__ b2,
    float* __restrict__ out)
{
    __shared__ float W2s[64 * 40];
    __shared__ float b2s[40];
    int tid = threadIdx.x;
    for (int i = tid; i < 64 * 40; i += 256) W2s[i] = W2[i];
    if (tid < 40) b2s[tid] = b2[tid];
    __syncthreads();

    int row = blockIdx.x * 256 + tid;
    if (row >= NN) return;

    float acc[40];
#pragma unroll
    for (int j = 0; j < 40; j++) acc[j] = b2s[j];

    const float4* h4 = g_h + row * 16;
#pragma unroll
    for (int k4 = 0; k4 < 16; k4++) {
        float4 hv = h4[k4];
#pragma unroll
        for (int kk = 0; kk < 4; kk++) {
            float hs = (kk == 0) ? hv.x : (kk == 1) ? hv.y : (kk == 2) ? hv.z : hv.w;
            const float* wrow = &W2s[(k4 * 4 + kk) * 40];
#pragma unroll
            for (int j = 0; j < 40; j++)
                acc[j] += hs * wrow[j];
        }
    }
#pragma unroll
    for (int j = 0; j < 40; j++)
        out[row * 40 + j] = acc[j];
}

// ---------------- launch ---------------------------------------------------
extern "C" void kernel_launch(void* const* d_in, const int* in_sizes, int n_in,
                              void* d_out, int out_size) {
    const float* x  = (const float*)d_in[0];
    const int*   ei = (const int*)d_in[1];     // int32! (jax default, no x64)
    const float* W1 = (const float*)d_in[2];
    const float* b1 = (const float*)d_in[3];
    const float* cw = (const float*)d_in[4];
    const float* W2 = (const float*)d_in[5];
    const float* b2 = (const float*)d_in[6];
    float*       out = (float*)d_out;

    deg_zero_k<<<(NN + 255) / 256, 256>>>();
    deg_count_k<<<(EE + 255) / 256, 256>>>(ei);
    dinv_k<<<(NN + 255) / 256, 256>>>();
    scan1_k<<<NB1, 512>>>();
    scan2_k<<<1, 256>>>();
    scan3_k<<<NB1, 512>>>();
    fill_k<<<(EE + 255) / 256, 256>>>(ei);
    mfuse_k<<<(NLAYERS * HID_ * HID_ + 255) / 256, 256>>>(cw);

    // h0 = relu(x @ W1 + b1)
    gemm_k<128, 0, true, true><<<(NN + 63) / 64, 256>>>(x, W1, b1, 0);

    for (int l = 0; l < NLAYERS; l++) {
        int use_h0 = (l == 0) ? 1 : 0;
        gather_k<<<(NN * 16 + 255) / 256, 256>>>(use_h0);
        gemm_k<64, 1, false, false><<<(NN + 63) / 64, 256>>>(nullptr, nullptr, nullptr, l);
    }

    final_k<<<(NN + 255) / 256, 256>>>(W2, b2, out);
}

// round 8
// speedup vs baseline: 1.0537x; 1.0537x over previous
#include <cuda_runtime.h>
#include <math.h>

#define NN      100000
#define EE      1600000
#define DIN_    128
#define HID_    64
#define DOUT_   40
#define NLAYERS 8
#define NB1     ((NN + 511) / 512)   // 196 scan blocks

// ---------------- scratch (device globals; no allocation allowed) ----------
__device__ int    g_degi[NN];
__device__ float  g_dinv[NN];
__device__ int    g_off[NN];
__device__ int    g_cur[NN];
__device__ int    g_bsum[256];
__device__ int    g_boff[256];
__device__ int    g_csrs[EE];
__device__ float  g_csrw[EE];
__device__ float4 g_h0[NN * 16];
__device__ float4 g_ha[NN * 16];
__device__ float4 g_hb[NN * 16];
__device__ float  g_M[NLAYERS * HID_ * HID_];

// ---------------- graph prep (edge_index is INT32) -------------------------
__global__ void deg_zero_k() {
    int i = blockIdx.x * blockDim.x + threadIdx.x;
    if (i < NN) g_degi[i] = 0;
}

__global__ void deg_count_k(const int* __restrict__ ei) {
    int e = blockIdx.x * blockDim.x + threadIdx.x;
    if (e < EE) {
        int d = ei[EE + e];
        if (d >= 0 && d < NN) atomicAdd(&g_degi[d], 1);
    }
}

__global__ void dinv_k() {
    int i = blockIdx.x * blockDim.x + threadIdx.x;
    if (i < NN) g_dinv[i] = rsqrtf((float)g_degi[i] + 1.0f);  // +1 self-loop
}

// --- exclusive scan over g_degi -> g_off: padded Hillis-Steele --------------
__global__ void scan1_k() {
    __shared__ int s[1024];
    int t = threadIdx.x;
    int i = blockIdx.x * 512 + t;
    int v = (i < NN) ? g_degi[i] : 0;
    s[t] = 0;
    s[512 + t] = v;
    __syncthreads();
#pragma unroll
    for (int d = 1; d < 512; d <<= 1) {
        int u = s[512 + t - d];
        __syncthreads();
        s[512 + t] += u;
        __syncthreads();
    }
    if (i < NN) g_off[i] = s[512 + t] - v;
    if (t == 511) g_bsum[blockIdx.x] = s[512 + 511];
}

__global__ void scan2_k() {
    __shared__ int s[512];
    int t = threadIdx.x;
    int v = (t < NB1) ? g_bsum[t] : 0;
    s[t] = 0;
    s[256 + t] = v;
    __syncthreads();
#pragma unroll
    for (int d = 1; d < 256; d <<= 1) {
        int u = s[256 + t - d];
        __syncthreads();
        s[256 + t] += u;
        __syncthreads();
    }
    g_boff[t] = s[256 + t] - v;
}

__global__ void scan3_k() {
    int i = blockIdx.x * 512 + threadIdx.x;
    if (i < NN) {
        int o = g_off[i] + g_boff[blockIdx.x];
        g_off[i] = o;
        g_cur[i] = o;
    }
}

__global__ void fill_k(const int* __restrict__ ei) {
    int e = blockIdx.x * blockDim.x + threadIdx.x;
    if (e < EE) {
        int s = ei[e];
        int d = ei[EE + e];
        if (s >= 0 && s < NN && d >= 0 && d < NN) {
            int pos = atomicAdd(&g_cur[d], 1);
            g_csrs[pos] = s;
            g_csrw[pos] = g_dinv[s] * g_dinv[d];
        }
    }
}

// M_l = (1-beta)*I + beta*W_l
__global__ void mfuse_k(const float* __restrict__ cw) {
    int idx = blockIdx.x * blockDim.x + threadIdx.x;
    if (idx < NLAYERS * HID_ * HID_) {
        int l = idx >> 12;
        int rc = idx & 4095;
        int r = rc >> 6, c = rc & 63;
        float beta = logf(0.5f / (float)(l + 1) + 1.0f);
        float v = beta * cw[idx];
        if (r == c) v += 1.0f - beta;
        g_M[idx] = v;
    }
}

// ---------------- fused layer: gather + residual + GEMM + relu -------------
// h_out = relu( [0.9*(dinv^2 h_in + sum w h_in[src]) + 0.1 h0] @ M_l )
// Double-buffered: h_in and h_out are DIFFERENT arrays (no cross-block race).
__global__ void __launch_bounds__(256) layer_k(int layer) {
    __shared__ float As[64 * 68];   // transposed A tile: As[k][r]
    __shared__ float Bs[64 * 64];

    // ping-pong buffer selection (layer 0 reads h0)
    const float4* __restrict__ h4 =
        (layer == 0) ? g_h0 : ((layer & 1) ? g_ha : g_hb);
    float4* __restrict__ hout = (layer & 1) ? g_hb : g_ha;

    int tid = threadIdx.x;
    int row0 = blockIdx.x << 6;

    // Load M_l
    const float* __restrict__ B = g_M + layer * 4096;
    for (int i = tid; i < 4096; i += 256)
        Bs[i] = B[i];

    // Gather phase: 4 passes x (16 rows x 16 lanes)
    int j = tid & 15;          // feature float4 index 0..15
    int rbase = tid >> 4;      // 0..15
#pragma unroll
    for (int p = 0; p < 4; p++) {
        int rl = p * 16 + rbase;       // local row 0..63
        int row = row0 + rl;
        float4 acc = make_float4(0.f, 0.f, 0.f, 0.f);
        if (row < NN) {
            float di = g_dinv[row];
            float ws = di * di;
            float4 hv = h4[row * 16 + j];
            acc.x = ws * hv.x; acc.y = ws * hv.y;
            acc.z = ws * hv.z; acc.w = ws * hv.w;

            int beg = g_off[row];
            int end = beg + g_degi[row];
            int e = beg;
            for (; e + 1 < end; e += 2) {
                int s0 = g_csrs[e];
                int s1 = g_csrs[e + 1];
                float w0 = g_csrw[e];
                float w1 = g_csrw[e + 1];
                float4 v0 = h4[s0 * 16 + j];
                float4 v1 = h4[s1 * 16 + j];
                acc.x += w0 * v0.x + w1 * v1.x;
                acc.y += w0 * v0.y + w1 * v1.y;
                acc.z += w0 * v0.z + w1 * v1.z;
                acc.w += w0 * v0.w + w1 * v1.w;
            }
            if (e < end) {
                int s0 = g_csrs[e];
                float w0 = g_csrw[e];
                float4 v0 = h4[s0 * 16 + j];
                acc.x += w0 * v0.x;
                acc.y += w0 * v0.y;
                acc.z += w0 * v0.z;
                acc.w += w0 * v0.w;
            }

            float4 h0v = g_h0[row * 16 + j];
            acc.x = 0.9f * acc.x + 0.1f * h0v.x;
            acc.y = 0.9f * acc.y + 0.1f * h0v.y;
            acc.z = 0.9f * acc.z + 0.1f * h0v.z;
            acc.w = 0.9f * acc.w + 0.1f * h0v.w;
        }
        int k = j << 2;
        As[(k + 0) * 68 + rl] = acc.x;
        As[(k + 1) * 68 + rl] = acc.y;
        As[(k + 2) * 68 + rl] = acc.z;
        As[(k + 3) * 68 + rl] = acc.w;
    }
    __syncthreads();

    // GEMM phase
    int tx = tid & 15;
    int ty = tid >> 4;
    float acc[4][4] = {};
#pragma unroll 16
    for (int k = 0; k < 64; k++) {
        float4 a4 = *(const float4*)&As[k * 68 + (ty << 2)];
        float4 b4 = *(const float4*)&Bs[(k << 6) + (tx << 2)];
        acc[0][0] += a4.x * b4.x; acc[0][1] += a4.x * b4.y;
        acc[0][2] += a4.x * b4.z; acc[0][3] += a4.x * b4.w;
        acc[1][0] += a4.y * b4.x; acc[1][1] += a4.y * b4.y;
        acc[1][2] += a4.y * b4.z; acc[1][3] += a4.y * b4.w;
        acc[2][0] += a4.z * b4.x; acc[2][1] += a4.z * b4.y;
        acc[2][2] += a4.z * b4.z; acc[2][3] += a4.z * b4.w;
        acc[3][0] += a4.w * b4.x; acc[3][1] += a4.w * b4.y;
        acc[3][2] += a4.w * b4.z; acc[3][3] += a4.w * b4.w;
    }

#pragma unroll
    for (int i = 0; i < 4; i++) {
        int r = row0 + (ty << 2) + i;
        if (r < NN) {
            float4 o = make_float4(fmaxf(acc[i][0], 0.f), fmaxf(acc[i][1], 0.f),
                                   fmaxf(acc[i][2], 0.f), fmaxf(acc[i][3], 0.f));
            hout[r * 16 + tx] = o;
        }
    }
}

// ---------------- GEMM1: h0 = relu(x @ W1 + b1)  (K=128) -------------------
__global__ void __launch_bounds__(256) gemm1_k(
    const float* __restrict__ Aext,
    const float* __restrict__ Bext,
    const float* __restrict__ bias)
{
    __shared__ float As[64 * 68];
    __shared__ float Bs[64 * 64];
    __shared__ float bsh[64];

    int tid = threadIdx.x;
    int tx = tid & 15;
    int ty = tid >> 4;
    int row0 = blockIdx.x << 6;

    if (tid < 64) bsh[tid] = bias[tid];

    float acc[4][4] = {};

#pragma unroll
    for (int kc = 0; kc < 128; kc += 64) {
        for (int i = tid; i < 64 * 64; i += 256)
            Bs[i] = Bext[kc * 64 + i];
        {
            int r = tid >> 2;
            int fq = tid & 3;
            int grow = row0 + r;
            bool ok = grow < NN;
#pragma unroll
            for (int q = 0; q < 4; q++) {
                int f4 = fq * 4 + q;
                float4 v = make_float4(0.f, 0.f, 0.f, 0.f);
                if (ok)
                    v = ((const float4*)Aext)[grow * 32 + (kc >> 2) + f4];
                int kk = f4 << 2;
                As[(kk + 0) * 68 + r] = v.x;
                As[(kk + 1) * 68 + r] = v.y;
                As[(kk + 2) * 68 + r] = v.z;
                As[(kk + 3) * 68 + r] = v.w;
            }
        }
        __syncthreads();

#pragma unroll 16
        for (int k = 0; k < 64; k++) {
            float4 a4 = *(const float4*)&As[k * 68 + (ty << 2)];
            float4 b4 = *(const float4*)&Bs[(k << 6) + (tx << 2)];
            acc[0][0] += a4.x * b4.x; acc[0][1] += a4.x * b4.y;
            acc[0][2] += a4.x * b4.z; acc[0][3] += a4.x * b4.w;
            acc[1][0] += a4.y * b4.x; acc[1][1] += a4.y * b4.y;
            acc[1][2] += a4.y * b4.z; acc[1][3] += a4.y * b4.w;
            acc[2][0] += a4.z * b4.x; acc[2][1] += a4.z * b4.y;
            acc[2][2] += a4.z * b4.z; acc[2][3] += a4.z * b4.w;
            acc[3][0] += a4.w * b4.x; acc[3][1] += a4.w * b4.y;
            acc[3][2] += a4.w * b4.z; acc[3][3] += a4.w * b4.w;
        }
        __syncthreads();
    }

#pragma unroll
    for (int i = 0; i < 4; i++) {
        int r = row0 + (ty << 2) + i;
        if (r < NN) {
            float4 o;
            o.x = fmaxf(acc[i][0] + bsh[tx * 4 + 0], 0.f);
            o.y = fmaxf(acc[i][1] + bsh[tx * 4 + 1], 0.f);
            o.z = fmaxf(acc[i][2] + bsh[tx * 4 + 2], 0.f);
            o.w = fmaxf(acc[i][3] + bsh[tx * 4 + 3], 0.f);
            g_h0[r * 16 + tx] = o;
        }
    }
}

// ---------------- final GEMM: out = h @ W2 + b2  ([N,64]@[64,40]) ----------
__global__ void __launch_bounds__(256) final_k(
    const float* __restrict__ W2, const float* __restrict__ b2,
    float* __restrict__ out)
{
    __shared__ float W2s[64 * 40];
    __shared__ float b2s[40];
    int tid = threadIdx.x;
    for (int i = tid; i < 64 * 40; i += 256) W2s[i] = W2[i];
    if (tid < 40) b2s[tid] = b2[tid];
    __syncthreads();

    int row = blockIdx.x * 256 + tid;
    if (row >= NN) return;

    float acc[40];
#pragma unroll
    for (int j = 0; j < 40; j++) acc[j] = b2s[j];

    // last layer is NLAYERS-1 = 7 (odd) -> wrote g_hb
    const float4* h4 = g_hb + row * 16;
#pragma unroll
    for (int k4 = 0; k4 < 16; k4++) {
        float4 hv = h4[k4];
#pragma unroll
        for (int kk = 0; kk < 4; kk++) {
            float hs = (kk == 0) ? hv.x : (kk == 1) ? hv.y : (kk == 2) ? hv.z : hv.w;
            const float* wrow = &W2s[(k4 * 4 + kk) * 40];
#pragma unroll
            for (int j = 0; j < 40; j++)
                acc[j] += hs * wrow[j];
        }
    }
#pragma unroll
    for (int j = 0; j < 40; j++)
        out[row * 40 + j] = acc[j];
}

// ---------------- launch ---------------------------------------------------
extern "C" void kernel_launch(void* const* d_in, const int* in_sizes, int n_in,
                              void* d_out, int out_size) {
    const float* x  = (const float*)d_in[0];
    const int*   ei = (const int*)d_in[1];     // int32 (jax default, no x64)
    const float* W1 = (const float*)d_in[2];
    const float* b1 = (const float*)d_in[3];
    const float* cw = (const float*)d_in[4];
    const float* W2 = (const float*)d_in[5];
    const float* b2 = (const float*)d_in[6];
    float*       out = (float*)d_out;

    deg_zero_k<<<(NN + 255) / 256, 256>>>();
    deg_count_k<<<(EE + 255) / 256, 256>>>(ei);
    dinv_k<<<(NN + 255) / 256, 256>>>();
    scan1_k<<<NB1, 512>>>();
    scan2_k<<<1, 256>>>();
    scan3_k<<<NB1, 512>>>();
    fill_k<<<(EE + 255) / 256, 256>>>(ei);
    mfuse_k<<<(NLAYERS * HID_ * HID_ + 255) / 256, 256>>>(cw);

    gemm1_k<<<(NN + 63) / 64, 256>>>(x, W1, b1);

    for (int l = 0; l < NLAYERS; l++)
        layer_k<<<(NN + 63) / 64, 256>>>(l);

    final_k<<<(NN + 255) / 256, 256>>>(W2, b2, out);
}

// round 9
// speedup vs baseline: 1.2616x; 1.1973x over previous
#include <cuda_runtime.h>
#include <cuda_fp16.h>
#include <math.h>

#define NN      100000
#define EE      1600000
#define DIN_    128
#define HID_    64
#define DOUT_   40
#define NLAYERS 8
#define NB1     ((NN + 511) / 512)   // 196 scan blocks

// ---------------- scratch (device globals; no allocation allowed) ----------
__device__ int    g_degi[NN];
__device__ float  g_dinv[NN];
__device__ int    g_off[NN];
__device__ int    g_cur[NN];
__device__ int    g_bsum[256];
__device__ int    g_boff[256];
__device__ int    g_csrs[EE];
__device__ float  g_csrw[EE];      // pre-scaled by 0.9
__device__ uint2  g_h0h[NN * 16];  // fp16 h0: 64 halves/row = 16 uint2
__device__ uint2  g_hah[NN * 16];
__device__ uint2  g_hbh[NN * 16];
__device__ float  g_M[NLAYERS * HID_ * HID_];

// fp16 pack/unpack helpers
__device__ __forceinline__ float4 u2f4(uint2 u) {
    __half2 a = *(__half2*)&u.x;
    __half2 b = *(__half2*)&u.y;
    float2 fa = __half22float2(a), fb = __half22float2(b);
    return make_float4(fa.x, fa.y, fb.x, fb.y);
}
__device__ __forceinline__ uint2 f4u2(float4 v) {
    __half2 a = __floats2half2_rn(v.x, v.y);
    __half2 b = __floats2half2_rn(v.z, v.w);
    uint2 u;
    u.x = *(unsigned*)&a;
    u.y = *(unsigned*)&b;
    return u;
}

// ---------------- graph prep (edge_index is INT32) -------------------------
__global__ void deg_zero_k() {
    int i = blockIdx.x * blockDim.x + threadIdx.x;
    if (i < NN) g_degi[i] = 0;
}

__global__ void deg_count_k(const int* __restrict__ ei) {
    int e = blockIdx.x * blockDim.x + threadIdx.x;
    if (e < EE) {
        int d = ei[EE + e];
        if (d >= 0 && d < NN) atomicAdd(&g_degi[d], 1);
    }
}

__global__ void dinv_k() {
    int i = blockIdx.x * blockDim.x + threadIdx.x;
    if (i < NN) g_dinv[i] = rsqrtf((float)g_degi[i] + 1.0f);  // +1 self-loop
}

// --- exclusive scan over g_degi -> g_off: padded Hillis-Steele --------------
__global__ void scan1_k() {
    __shared__ int s[1024];
    int t = threadIdx.x;
    int i = blockIdx.x * 512 + t;
    int v = (i < NN) ? g_degi[i] : 0;
    s[t] = 0;
    s[512 + t] = v;
    __syncthreads();
#pragma unroll
    for (int d = 1; d < 512; d <<= 1) {
        int u = s[512 + t - d];
        __syncthreads();
        s[512 + t] += u;
        __syncthreads();
    }
    if (i < NN) g_off[i] = s[512 + t] - v;
    if (t == 511) g_bsum[blockIdx.x] = s[512 + 511];
}

__global__ void scan2_k() {
    __shared__ int s[512];
    int t = threadIdx.x;
    int v = (t < NB1) ? g_bsum[t] : 0;
    s[t] = 0;
    s[256 + t] = v;
    __syncthreads();
#pragma unroll
    for (int d = 1; d < 256; d <<= 1) {
        int u = s[256 + t - d];
        __syncthreads();
        s[256 + t] += u;
        __syncthreads();
    }
    g_boff[t] = s[256 + t] - v;
}

__global__ void scan3_k() {
    int i = blockIdx.x * 512 + threadIdx.x;
    if (i < NN) {
        int o = g_off[i] + g_boff[blockIdx.x];
        g_off[i] = o;
        g_cur[i] = o;
    }
}

__global__ void fill_k(const int* __restrict__ ei) {
    int e = blockIdx.x * blockDim.x + threadIdx.x;
    if (e < EE) {
        int s = ei[e];
        int d = ei[EE + e];
        if (s >= 0 && s < NN && d >= 0 && d < NN) {
            int pos = atomicAdd(&g_cur[d], 1);
            g_csrs[pos] = s;
            g_csrw[pos] = 0.9f * g_dinv[s] * g_dinv[d];   // fold (1-alpha)
        }
    }
}

// M_l = (1-beta)*I + beta*W_l
__global__ void mfuse_k(const float* __restrict__ cw) {
    int idx = blockIdx.x * blockDim.x + threadIdx.x;
    if (idx < NLAYERS * HID_ * HID_) {
        int l = idx >> 12;
        int rc = idx & 4095;
        int r = rc >> 6, c = rc & 63;
        float beta = logf(0.5f / (float)(l + 1) + 1.0f);
        float v = beta * cw[idx];
        if (r == c) v += 1.0f - beta;
        g_M[idx] = v;
    }
}

// ---------------- fused layer: gather + residual + GEMM + relu -------------
// h_out = relu( [0.9*(dinv^2 h_in + sum w h_in[src]) + 0.1 h0] @ M_l )
// h stored fp16 (uint2 = 4 halves per lane), accumulate fp32.
__global__ void __launch_bounds__(256) layer_k(int layer) {
    __shared__ float As[64 * 68];   // transposed A tile: As[k][r]
    __shared__ float Bs[64 * 64];

    const uint2* __restrict__ hin =
        (layer == 0) ? g_h0h : ((layer & 1) ? g_hah : g_hbh);
    uint2* __restrict__ hout = (layer & 1) ? g_hbh : g_hah;

    int tid = threadIdx.x;
    int row0 = blockIdx.x << 6;

    const float* __restrict__ B = g_M + layer * 4096;
    for (int i = tid; i < 4096; i += 256)
        Bs[i] = B[i];

    int j = tid & 15;          // feature uint2 index 0..15 (4 halves each)
    int rbase = tid >> 4;      // 0..15
#pragma unroll
    for (int p = 0; p < 4; p++) {
        int rl = p * 16 + rbase;
        int row = row0 + rl;
        float4 acc = make_float4(0.f, 0.f, 0.f, 0.f);
        if (row < NN) {
            float di = g_dinv[row];
            float ws = 0.9f * di * di;
            float4 hv = u2f4(hin[row * 16 + j]);
            acc.x = ws * hv.x; acc.y = ws * hv.y;
            acc.z = ws * hv.z; acc.w = ws * hv.w;

            int beg = g_off[row];
            int end = beg + g_degi[row];
            int e = beg;
            for (; e + 3 < end; e += 4) {
                int s0 = g_csrs[e];
                int s1 = g_csrs[e + 1];
                int s2 = g_csrs[e + 2];
                int s3 = g_csrs[e + 3];
                float w0 = g_csrw[e];
                float w1 = g_csrw[e + 1];
                float w2 = g_csrw[e + 2];
                float w3 = g_csrw[e + 3];
                float4 v0 = u2f4(hin[s0 * 16 + j]);
                float4 v1 = u2f4(hin[s1 * 16 + j]);
                float4 v2 = u2f4(hin[s2 * 16 + j]);
                float4 v3 = u2f4(hin[s3 * 16 + j]);
                acc.x += w0 * v0.x + w1 * v1.x + w2 * v2.x + w3 * v3.x;
                acc.y += w0 * v0.y + w1 * v1.y + w2 * v2.y + w3 * v3.y;
                acc.z += w0 * v0.z + w1 * v1.z + w2 * v2.z + w3 * v3.z;
                acc.w += w0 * v0.w + w1 * v1.w + w2 * v2.w + w3 * v3.w;
            }
            for (; e < end; e++) {
                int s0 = g_csrs[e];
                float w0 = g_csrw[e];
                float4 v0 = u2f4(hin[s0 * 16 + j]);
                acc.x += w0 * v0.x;
                acc.y += w0 * v0.y;
                acc.z += w0 * v0.z;
                acc.w += w0 * v0.w;
            }

            float4 h0v = u2f4(g_h0h[row * 16 + j]);
            acc.x += 0.1f * h0v.x;
            acc.y += 0.1f * h0v.y;
            acc.z += 0.1f * h0v.z;
            acc.w += 0.1f * h0v.w;
        }
        int k = j << 2;
        As[(k + 0) * 68 + rl] = acc.x;
        As[(k + 1) * 68 + rl] = acc.y;
        As[(k + 2) * 68 + rl] = acc.z;
        As[(k + 3) * 68 + rl] = acc.w;
    }
    __syncthreads();

    // GEMM phase (fp32)
    int tx = tid & 15;
    int ty = tid >> 4;
    float acc[4][4] = {};
#pragma unroll 16
    for (int k = 0; k < 64; k++) {
        float4 a4 = *(const float4*)&As[k * 68 + (ty << 2)];
        float4 b4 = *(const float4*)&Bs[(k << 6) + (tx << 2)];
        acc[0][0] += a4.x * b4.x; acc[0][1] += a4.x * b4.y;
        acc[0][2] += a4.x * b4.z; acc[0][3] += a4.x * b4.w;
        acc[1][0] += a4.y * b4.x; acc[1][1] += a4.y * b4.y;
        acc[1][2] += a4.y * b4.z; acc[1][3] += a4.y * b4.w;
        acc[2][0] += a4.z * b4.x; acc[2][1] += a4.z * b4.y;
        acc[2][2] += a4.z * b4.z; acc[2][3] += a4.z * b4.w;
        acc[3][0] += a4.w * b4.x; acc[3][1] += a4.w * b4.y;
        acc[3][2] += a4.w * b4.z; acc[3][3] += a4.w * b4.w;
    }

#pragma unroll
    for (int i = 0; i < 4; i++) {
        int r = row0 + (ty << 2) + i;
        if (r < NN) {
            float4 o = make_float4(fmaxf(acc[i][0], 0.f), fmaxf(acc[i][1], 0.f),
                                   fmaxf(acc[i][2], 0.f), fmaxf(acc[i][3], 0.f));
            hout[r * 16 + tx] = f4u2(o);
        }
    }
}

// ---------------- GEMM1: h0 = relu(x @ W1 + b1), stored fp16 ---------------
__global__ void __launch_bounds__(256) gemm1_k(
    const float* __restrict__ Aext,
    const float* __restrict__ Bext,
    const float* __restrict__ bias)
{
    __shared__ float As[64 * 68];
    __shared__ float Bs[64 * 64];
    __shared__ float bsh[64];

    int tid = threadIdx.x;
    int tx = tid & 15;
    int ty = tid >> 4;
    int row0 = blockIdx.x << 6;

    if (tid < 64) bsh[tid] = bias[tid];

    float acc[4][4] = {};

#pragma unroll
    for (int kc = 0; kc < 128; kc += 64) {
        for (int i = tid; i < 64 * 64; i += 256)
            Bs[i] = Bext[kc * 64 + i];
        {
            int r = tid >> 2;
            int fq = tid & 3;
            int grow = row0 + r;
            bool ok = grow < NN;
#pragma unroll
            for (int q = 0; q < 4; q++) {
                int f4 = fq * 4 + q;
                float4 v = make_float4(0.f, 0.f, 0.f, 0.f);
                if (ok)
                    v = ((const float4*)Aext)[grow * 32 + (kc >> 2) + f4];
                int kk = f4 << 2;
                As[(kk + 0) * 68 + r] = v.x;
                As[(kk + 1) * 68 + r] = v.y;
                As[(kk + 2) * 68 + r] = v.z;
                As[(kk + 3) * 68 + r] = v.w;
            }
        }
        __syncthreads();

#pragma unroll 16
        for (int k = 0; k < 64; k++) {
            float4 a4 = *(const float4*)&As[k * 68 + (ty << 2)];
            float4 b4 = *(const float4*)&Bs[(k << 6) + (tx << 2)];
            acc[0][0] += a4.x * b4.x; acc[0][1] += a4.x * b4.y;
            acc[0][2] += a4.x * b4.z; acc[0][3] += a4.x * b4.w;
            acc[1][0] += a4.y * b4.x; acc[1][1] += a4.y * b4.y;
            acc[1][2] += a4.y * b4.z; acc[1][3] += a4.y * b4.w;
            acc[2][0] += a4.z * b4.x; acc[2][1] += a4.z * b4.y;
            acc[2][2] += a4.z * b4.z; acc[2][3] += a4.z * b4.w;
            acc[3][0] += a4.w * b4.x; acc[3][1] += a4.w * b4.y;
            acc[3][2] += a4.w * b4.z; acc[3][3] += a4.w * b4.w;
        }
        __syncthreads();
    }

#pragma unroll
    for (int i = 0; i < 4; i++) {
        int r = row0 + (ty << 2) + i;
        if (r < NN) {
            float4 o;
            o.x = fmaxf(acc[i][0] + bsh[tx * 4 + 0], 0.f);
            o.y = fmaxf(acc[i][1] + bsh[tx * 4 + 1], 0.f);
            o.z = fmaxf(acc[i][2] + bsh[tx * 4 + 2], 0.f);
            o.w = fmaxf(acc[i][3] + bsh[tx * 4 + 3], 0.f);
            g_h0h[r * 16 + tx] = f4u2(o);
        }
    }
}

// ---------------- final GEMM: out = h @ W2 + b2  ([N,64]@[64,40]) ----------
__global__ void __launch_bounds__(256) final_k(
    const float* __restrict__ W2, const float* __restrict__ b2,
    float* __restrict__ out)
{
    __shared__ float W2s[64 * 40];
    __shared__ float b2s[40];
    int tid = threadIdx.x;
    for (int i = tid; i < 64 * 40; i += 256) W2s[i] = W2[i];
    if (tid < 40) b2s[tid] = b2[tid];
    __syncthreads();

    int row = blockIdx.x * 256 + tid;
    if (row >= NN) return;

    float acc[40];
#pragma unroll
    for (int j = 0; j < 40; j++) acc[j] = b2s[j];

    // last layer is 7 (odd) -> wrote g_hbh
    const uint4* hr = (const uint4*)(g_hbh + row * 16);   // 8 x uint4 = 64 halves
#pragma unroll
    for (int q = 0; q < 8; q++) {
        uint4 u = hr[q];
        float4 f0 = u2f4(make_uint2(u.x, u.y));
        float4 f1 = u2f4(make_uint2(u.z, u.w));
        float hs[8] = {f0.x, f0.y, f0.z, f0.w, f1.x, f1.y, f1.z, f1.w};
#pragma unroll
        for (int kk = 0; kk < 8; kk++) {
            const float* wrow = &W2s[(q * 8 + kk) * 40];
#pragma unroll
            for (int jj = 0; jj < 40; jj++)
                acc[jj] += hs[kk] * wrow[jj];
        }
    }
#pragma unroll
    for (int jj = 0; jj < 40; jj++)
        out[row * 40 + jj] = acc[jj];
}

// ---------------- launch ---------------------------------------------------
extern "C" void kernel_launch(void* const* d_in, const int* in_sizes, int n_in,
                              void* d_out, int out_size) {
    const float* x  = (const float*)d_in[0];
    const int*   ei = (const int*)d_in[1];     // int32 (jax default, no x64)
    const float* W1 = (const float*)d_in[2];
    const float* b1 = (const float*)d_in[3];
    const float* cw = (const float*)d_in[4];
    const float* W2 = (const float*)d_in[5];
    const float* b2 = (const float*)d_in[6];
    float*       out = (float*)d_out;

    deg_zero_k<<<(NN + 255) / 256, 256>>>();
    deg_count_k<<<(EE + 255) / 256, 256>>>(ei);
    dinv_k<<<(NN + 255) / 256, 256>>>();
    scan1_k<<<NB1, 512>>>();
    scan2_k<<<1, 256>>>();
    scan3_k<<<NB1, 512>>>();
    fill_k<<<(EE + 255) / 256, 256>>>(ei);
    mfuse_k<<<(NLAYERS * HID_ * HID_ + 255) / 256, 256>>>(cw);

    gemm1_k<<<(NN + 63) / 64, 256>>>(x, W1, b1);

    for (int l = 0; l < NLAYERS; l++)
        layer_k<<<(NN + 63) / 64, 256>>>(l);

    final_k<<<(NN + 255) / 256, 256>>>(W2, b2, out);
}

// round 10
// speedup vs baseline: 1.9351x; 1.5338x over previous
#include <cuda_runtime.h>
#include <cuda_fp16.h>
#include <math.h>

#define NN      100000
#define EE      1600000
#define DIN_    128
#define HID_    64
#define DOUT_   40
#define NLAYERS 8
#define NB1     ((NN + 511) / 512)   // 196 scan blocks

// ---------------- scratch (device globals; no allocation allowed) ----------
__device__ int    g_degi[NN];
__device__ float  g_dinv[NN];
__device__ int    g_off[NN];
__device__ int    g_cur[NN];
__device__ int    g_bsum[256];
__device__ int    g_boff[256];
__device__ uint2  g_edge[EE];       // {src, __float_as_uint(0.9*w)}
__device__ uint4  g_h0h[NN * 8];    // fp16 h: 64 halves/row = 8 uint4
__device__ uint4  g_hah[NN * 8];
__device__ uint4  g_hbh[NN * 8];
__device__ __half g_Mh[NLAYERS * HID_ * HID_];
__device__ __half g_W1h[DIN_ * HID_];

// ---------------- helpers ---------------------------------------------------
__device__ __forceinline__ void fma8(float* acc, uint4 u, float w) {
    float2 p;
    p = __half22float2(*(__half2*)&u.x); acc[0] += w * p.x; acc[1] += w * p.y;
    p = __half22float2(*(__half2*)&u.y); acc[2] += w * p.x; acc[3] += w * p.y;
    p = __half22float2(*(__half2*)&u.z); acc[4] += w * p.x; acc[5] += w * p.y;
    p = __half22float2(*(__half2*)&u.w); acc[6] += w * p.x; acc[7] += w * p.y;
}

__device__ __forceinline__ void ldsm_x4(unsigned* r, unsigned addr) {
    asm volatile("ldmatrix.sync.aligned.m8n8.x4.shared.b16 {%0,%1,%2,%3}, [%4];"
                 : "=r"(r[0]), "=r"(r[1]), "=r"(r[2]), "=r"(r[3]) : "r"(addr));
}
__device__ __forceinline__ void ldsm_x4_t(unsigned* r, unsigned addr) {
    asm volatile("ldmatrix.sync.aligned.m8n8.x4.trans.shared.b16 {%0,%1,%2,%3}, [%4];"
                 : "=r"(r[0]), "=r"(r[1]), "=r"(r[2]), "=r"(r[3]) : "r"(addr));
}
__device__ __forceinline__ void mma_f16(float* d, const unsigned* a, const unsigned* b) {
    asm volatile(
        "mma.sync.aligned.m16n8k16.row.col.f32.f16.f16.f32 "
        "{%0,%1,%2,%3}, {%4,%5,%6,%7}, {%8,%9}, {%0,%1,%2,%3};"
        : "+f"(d[0]), "+f"(d[1]), "+f"(d[2]), "+f"(d[3])
        : "r"(a[0]), "r"(a[1]), "r"(a[2]), "r"(a[3]), "r"(b[0]), "r"(b[1]));
}

// ---------------- graph prep (edge_index is INT32) -------------------------
__global__ void deg_zero_k() {
    int i = blockIdx.x * blockDim.x + threadIdx.x;
    if (i < NN) g_degi[i] = 0;
}

__global__ void deg_count_k(const int* __restrict__ ei) {
    int e = blockIdx.x * blockDim.x + threadIdx.x;
    if (e < EE) {
        int d = ei[EE + e];
        if (d >= 0 && d < NN) atomicAdd(&g_degi[d], 1);
    }
}

__global__ void dinv_k() {
    int i = blockIdx.x * blockDim.x + threadIdx.x;
    if (i < NN) g_dinv[i] = rsqrtf((float)g_degi[i] + 1.0f);  // +1 self-loop
}

__global__ void scan1_k() {
    __shared__ int s[1024];
    int t = threadIdx.x;
    int i = blockIdx.x * 512 + t;
    int v = (i < NN) ? g_degi[i] : 0;
    s[t] = 0;
    s[512 + t] = v;
    __syncthreads();
#pragma unroll
    for (int d = 1; d < 512; d <<= 1) {
        int u = s[512 + t - d];
        __syncthreads();
        s[512 + t] += u;
        __syncthreads();
    }
    if (i < NN) g_off[i] = s[512 + t] - v;
    if (t == 511) g_bsum[blockIdx.x] = s[512 + 511];
}

__global__ void scan2_k() {
    __shared__ int s[512];
    int t = threadIdx.x;
    int v = (t < NB1) ? g_bsum[t] : 0;
    s[t] = 0;
    s[256 + t] = v;
    __syncthreads();
#pragma unroll
    for (int d = 1; d < 256; d <<= 1) {
        int u = s[256 + t - d];
        __syncthreads();
        s[256 + t] += u;
        __syncthreads();
    }
    g_boff[t] = s[256 + t] - v;
}

__global__ void scan3_k() {
    int i = blockIdx.x * 512 + threadIdx.x;
    if (i < NN) {
        int o = g_off[i] + g_boff[blockIdx.x];
        g_off[i] = o;
        g_cur[i] = o;
    }
}

__global__ void fill_k(const int* __restrict__ ei) {
    int e = blockIdx.x * blockDim.x + threadIdx.x;
    if (e < EE) {
        int s = ei[e];
        int d = ei[EE + e];
        if (s >= 0 && s < NN && d >= 0 && d < NN) {
            int pos = atomicAdd(&g_cur[d], 1);
            uint2 pe;
            pe.x = (unsigned)s;
            pe.y = __float_as_uint(0.9f * g_dinv[s] * g_dinv[d]);
            g_edge[pos] = pe;
        }
    }
}

// M_l = (1-beta)*I + beta*W_l, stored fp16
__global__ void mfuse_k(const float* __restrict__ cw) {
    int idx = blockIdx.x * blockDim.x + threadIdx.x;
    if (idx < NLAYERS * HID_ * HID_) {
        int l = idx >> 12;
        int rc = idx & 4095;
        int r = rc >> 6, c = rc & 63;
        float beta = logf(0.5f / (float)(l + 1) + 1.0f);
        float v = beta * cw[idx];
        if (r == c) v += 1.0f - beta;
        g_Mh[idx] = __float2half(v);
    }
}

__global__ void w1conv_k(const float* __restrict__ W1) {
    int idx = blockIdx.x * blockDim.x + threadIdx.x;
    if (idx < DIN_ * HID_) g_W1h[idx] = __float2half(W1[idx]);
}

// ---------------- fused layer: gather + residual + HMMA GEMM + relu --------
__global__ void __launch_bounds__(256) layer_k(int layer) {
    __shared__ __align__(16) __half Ah[64 * 72];   // row-major, stride 72 halves
    __shared__ __align__(16) __half Bh[64 * 72];

    const uint4* __restrict__ hin =
        (layer == 0) ? g_h0h : ((layer & 1) ? g_hah : g_hbh);
    uint4* __restrict__ hout = (layer & 1) ? g_hbh : g_hah;

    int tid = threadIdx.x;
    int row0 = blockIdx.x << 6;

    // load M_l (fp16) into Bh with padded stride
    {
        const unsigned* Mw = (const unsigned*)(g_Mh + layer * 4096);  // 2048 words
        unsigned* Bw = (unsigned*)Bh;
#pragma unroll
        for (int t = 0; t < 8; t++) {
            int v = t * 256 + tid;
            Bw[(v >> 5) * 36 + (v & 31)] = Mw[v];
        }
    }

    // gather: 8 lanes/row, uint4 (16B) per lane; 2 passes of 32 rows
    int j = tid & 7;
    int rbase = tid >> 3;
#pragma unroll
    for (int p = 0; p < 2; p++) {
        int rl = p * 32 + rbase;
        int row = row0 + rl;
        float acc[8] = {0.f, 0.f, 0.f, 0.f, 0.f, 0.f, 0.f, 0.f};
        if (row < NN) {
            float di = g_dinv[row];
            fma8(acc, hin[row * 8 + j], 0.9f * di * di);

            int beg = g_off[row];
            int deg = g_degi[row];
            const uint2* ep = g_edge + beg;
            int e = 0;
            for (; e + 3 < deg; e += 4) {
                uint2 q0 = ep[e], q1 = ep[e + 1], q2 = ep[e + 2], q3 = ep[e + 3];
                uint4 v0 = hin[q0.x * 8 + j];
                uint4 v1 = hin[q1.x * 8 + j];
                uint4 v2 = hin[q2.x * 8 + j];
                uint4 v3 = hin[q3.x * 8 + j];
                fma8(acc, v0, __uint_as_float(q0.y));
                fma8(acc, v1, __uint_as_float(q1.y));
                fma8(acc, v2, __uint_as_float(q2.y));
                fma8(acc, v3, __uint_as_float(q3.y));
            }
            for (; e < deg; e++) {
                uint2 q0 = ep[e];
                fma8(acc, hin[q0.x * 8 + j], __uint_as_float(q0.y));
            }
            fma8(acc, g_h0h[row * 8 + j], 0.1f);
        }
        __half2 p0 = __floats2half2_rn(acc[0], acc[1]);
        __half2 p1 = __floats2half2_rn(acc[2], acc[3]);
        __half2 p2 = __floats2half2_rn(acc[4], acc[5]);
        __half2 p3 = __floats2half2_rn(acc[6], acc[7]);
        uint4 st;
        st.x = *(unsigned*)&p0; st.y = *(unsigned*)&p1;
        st.z = *(unsigned*)&p2; st.w = *(unsigned*)&p3;
        *(uint4*)(Ah + rl * 72 + j * 8) = st;
    }
    __syncthreads();

    // HMMA: 8 warps, each 16x32 tile
    int w = tid >> 5, lane = tid & 31;
    int r0 = (w & 3) * 16;
    int n0 = (w >> 2) * 32;
    float d0[4] = {}, d1[4] = {}, d2[4] = {}, d3[4] = {};

    unsigned Asm = (unsigned)__cvta_generic_to_shared(Ah);
    unsigned Bsm = (unsigned)__cvta_generic_to_shared(Bh);
    int lr = lane & 15, lh = lane >> 4;
#pragma unroll
    for (int ks = 0; ks < 4; ks++) {
        int kk = ks * 16;
        unsigned a[4], b0[4], b1[4];
        ldsm_x4(a, Asm + ((r0 + lr) * 72 + kk + lh * 8) * 2);
        unsigned bad = Bsm + ((kk + lr) * 72 + n0 + lh * 8) * 2;
        ldsm_x4_t(b0, bad);
        ldsm_x4_t(b1, bad + 32);
        mma_f16(d0, a, b0 + 0);
        mma_f16(d1, a, b0 + 2);
        mma_f16(d2, a, b1 + 0);
        mma_f16(d3, a, b1 + 2);
    }

    // epilogue: relu, pack fp16, store
    int tg = lane >> 2, ti = lane & 3;
    unsigned* ho = (unsigned*)hout;   // 32 words per row
    int grow0 = row0 + r0 + tg;
    int grow1 = grow0 + 8;
    float* dd[4] = {d0, d1, d2, d3};
#pragma unroll
    for (int t = 0; t < 4; t++) {
        int col = n0 + t * 8 + ti * 2;
        __half2 lo = __floats2half2_rn(fmaxf(dd[t][0], 0.f), fmaxf(dd[t][1], 0.f));
        __half2 hi = __floats2half2_rn(fmaxf(dd[t][2], 0.f), fmaxf(dd[t][3], 0.f));
        if (grow0 < NN) ho[grow0 * 32 + (col >> 1)] = *(unsigned*)&lo;
        if (grow1 < NN) ho[grow1 * 32 + (col >> 1)] = *(unsigned*)&hi;
    }
}

// ---------------- GEMM1: h0 = relu(x @ W1 + b1), HMMA, K=128 ---------------
__global__ void __launch_bounds__(256) gemm1_k(
    const float* __restrict__ x, const float* __restrict__ bias)
{
    __shared__ __align__(16) __half Ah[64 * 72];
    __shared__ __align__(16) __half Bh[64 * 72];
    __shared__ float bsh[64];

    int tid = threadIdx.x;
    int row0 = blockIdx.x << 6;
    if (tid < 64) bsh[tid] = bias[tid];

    int w = tid >> 5, lane = tid & 31;
    int r0 = (w & 3) * 16;
    int n0 = (w >> 2) * 32;
    int lr = lane & 15, lh = lane >> 4;
    float d0[4] = {}, d1[4] = {}, d2[4] = {}, d3[4] = {};

    unsigned Asm = (unsigned)__cvta_generic_to_shared(Ah);
    unsigned Bsm = (unsigned)__cvta_generic_to_shared(Bh);

#pragma unroll
    for (int kc = 0; kc < 128; kc += 64) {
        // W1 chunk rows kc..kc+63 (fp16) -> Bh
        {
            const unsigned* Ww = (const unsigned*)(g_W1h + kc * 64);
            unsigned* Bw = (unsigned*)Bh;
#pragma unroll
            for (int t = 0; t < 8; t++) {
                int v = t * 256 + tid;
                Bw[(v >> 5) * 36 + (v & 31)] = Ww[v];
            }
        }
        // x chunk [64 rows x 64 cols fp32] -> fp16 Ah
        {
            int r = tid >> 2, q = tid & 3;
            int grow = row0 + r;
            float4 f0 = make_float4(0, 0, 0, 0), f1 = f0, f2 = f0, f3 = f0;
            if (grow < NN) {
                const float4* xr = (const float4*)x + grow * 32 + (kc >> 2) + q * 4;
                f0 = xr[0]; f1 = xr[1]; f2 = xr[2]; f3 = xr[3];
            }
            __half2 h0_ = __floats2half2_rn(f0.x, f0.y);
            __half2 h1_ = __floats2half2_rn(f0.z, f0.w);
            __half2 h2_ = __floats2half2_rn(f1.x, f1.y);
            __half2 h3_ = __floats2half2_rn(f1.z, f1.w);
            __half2 h4_ = __floats2half2_rn(f2.x, f2.y);
            __half2 h5_ = __floats2half2_rn(f2.z, f2.w);
            __half2 h6_ = __floats2half2_rn(f3.x, f3.y);
            __half2 h7_ = __floats2half2_rn(f3.z, f3.w);
            uint4 s0, s1;
            s0.x = *(unsigned*)&h0_; s0.y = *(unsigned*)&h1_;
            s0.z = *(unsigned*)&h2_; s0.w = *(unsigned*)&h3_;
            s1.x = *(unsigned*)&h4_; s1.y = *(unsigned*)&h5_;
            s1.z = *(unsigned*)&h6_; s1.w = *(unsigned*)&h7_;
            *(uint4*)(Ah + r * 72 + q * 16) = s0;
            *(uint4*)(Ah + r * 72 + q * 16 + 8) = s1;
        }
        __syncthreads();

#pragma unroll
        for (int ks = 0; ks < 4; ks++) {
            int kk = ks * 16;
            unsigned a[4], b0[4], b1[4];
            ldsm_x4(a, Asm + ((r0 + lr) * 72 + kk + lh * 8) * 2);
            unsigned bad = Bsm + ((kk + lr) * 72 + n0 + lh * 8) * 2;
            ldsm_x4_t(b0, bad);
            ldsm_x4_t(b1, bad + 32);
            mma_f16(d0, a, b0 + 0);
            mma_f16(d1, a, b0 + 2);
            mma_f16(d2, a, b1 + 0);
            mma_f16(d3, a, b1 + 2);
        }
        __syncthreads();
    }

    // epilogue: +bias, relu, pack fp16 -> g_h0h
    int tg = lane >> 2, ti = lane & 3;
    unsigned* ho = (unsigned*)g_h0h;
    int grow0 = row0 + r0 + tg;
    int grow1 = grow0 + 8;
    float* dd[4] = {d0, d1, d2, d3};
#pragma unroll
    for (int t = 0; t < 4; t++) {
        int col = n0 + t * 8 + ti * 2;
        float bx = bsh[col], by = bsh[col + 1];
        __half2 lo = __floats2half2_rn(fmaxf(dd[t][0] + bx, 0.f), fmaxf(dd[t][1] + by, 0.f));
        __half2 hi = __floats2half2_rn(fmaxf(dd[t][2] + bx, 0.f), fmaxf(dd[t][3] + by, 0.f));
        if (grow0 < NN) ho[grow0 * 32 + (col >> 1)] = *(unsigned*)&lo;
        if (grow1 < NN) ho[grow1 * 32 + (col >> 1)] = *(unsigned*)&hi;
    }
}

// ---------------- final GEMM: out = h @ W2 + b2  ([N,64]@[64,40]) ----------
__device__ __forceinline__ float4 u2f4(uint2 u) {
    __half2 a = *(__half2*)&u.x;
    __half2 b = *(__half2*)&u.y;
    float2 fa = __half22float2(a), fb = __half22float2(b);
    return make_float4(fa.x, fa.y, fb.x, fb.y);
}

__global__ void __launch_bounds__(256) final_k(
    const float* __restrict__ W2, const float* __restrict__ b2,
    float* __restrict__ out)
{
    __shared__ float W2s[64 * 40];
    __shared__ float b2s[40];
    int tid = threadIdx.x;
    for (int i = tid; i < 64 * 40; i += 256) W2s[i] = W2[i];
    if (tid < 40) b2s[tid] = b2[tid];
    __syncthreads();

    int row = blockIdx.x * 256 + tid;
    if (row >= NN) return;

    float acc[40];
#pragma unroll
    for (int j = 0; j < 40; j++) acc[j] = b2s[j];

    // last layer is 7 (odd) -> wrote g_hbh
    const uint4* hr = g_hbh + row * 8;
#pragma unroll
    for (int q = 0; q < 8; q++) {
        uint4 u = hr[q];
        float4 f0 = u2f4(make_uint2(u.x, u.y));
        float4 f1 = u2f4(make_uint2(u.z, u.w));
        float hs[8] = {f0.x, f0.y, f0.z, f0.w, f1.x, f1.y, f1.z, f1.w};
#pragma unroll
        for (int kk = 0; kk < 8; kk++) {
            const float* wrow = &W2s[(q * 8 + kk) * 40];
#pragma unroll
            for (int jj = 0; jj < 40; jj++)
                acc[jj] += hs[kk] * wrow[jj];
        }
    }
#pragma unroll
    for (int jj = 0; jj < 40; jj++)
        out[row * 40 + jj] = acc[jj];
}

// ---------------- launch ---------------------------------------------------
extern "C" void kernel_launch(void* const* d_in, const int* in_sizes, int n_in,
                              void* d_out, int out_size) {
    const float* x  = (const float*)d_in[0];
    const int*   ei = (const int*)d_in[1];     // int32 (jax default, no x64)
    const float* W1 = (const float*)d_in[2];
    const float* b1 = (const float*)d_in[3];
    const float* cw = (const float*)d_in[4];
    const float* W2 = (const float*)d_in[5];
    const float* b2 = (const float*)d_in[6];
    float*       out = (float*)d_out;

    deg_zero_k<<<(NN + 255) / 256, 256>>>();
    deg_count_k<<<(EE + 255) / 256, 256>>>(ei);
    dinv_k<<<(NN + 255) / 256, 256>>>();
    scan1_k<<<NB1, 512>>>();
    scan2_k<<<1, 256>>>();
    scan3_k<<<NB1, 512>>>();
    fill_k<<<(EE + 255) / 256, 256>>>(ei);
    mfuse_k<<<(NLAYERS * HID_ * HID_ + 255) / 256, 256>>>(cw);
    w1conv_k<<<(DIN_ * HID_ + 255) / 256, 256>>>(W1);

    gemm1_k<<<(NN + 63) / 64, 256>>>(x, b1);

    for (int l = 0; l < NLAYERS; l++)
        layer_k<<<(NN + 63) / 64, 256>>>(l);

    final_k<<<(NN + 255) / 256, 256>>>(W2, b2, out);
}